// round 6
// baseline (speedup 1.0000x reference)
#include <cuda_runtime.h>

// SequentialLoraA: y_large[b, r] = sum_d x[b,d] * A_large[wids_large[b], d, r]   (r<64)
//                  y_small[b, r] = sum_d x[256+b,d] * A_small[wids_small[b], d, r] (r<16)
//
// HARNESS NOTE: the reference produces float16 arrays, but this harness only
// carries float32/int32/bf16 — all f16 tensors arrive converted to FLOAT32
// (element counts unchanged). Output buffer is float32:
// y_large (256*64) followed by y_small (256*16).
//
// Inputs identified by element count (robust to metadata ordering):
//   x            : 512*4096      = 2,097,152   (f32)
//   wids_large   : 256                         (i32)  -- first size-256 buffer
//   wids_small   : 256                         (i32)  -- second size-256 buffer
//   lora_A_large : 128*4096*64   = 33,554,432  (f32)
//   lora_A_small : 128*4096*16   =  8,388,608  (f32)

#define D_DIM    4096
#define B_LARGE  256
#define B_SMALL  256
#define R_LARGE  64
#define R_SMALL  16

__global__ __launch_bounds__(256, 4)
void lora_a_kernel(const float* __restrict__ x,
                   const int*   __restrict__ wids_large,
                   const int*   __restrict__ wids_small,
                   const float* __restrict__ A_large,
                   const float* __restrict__ A_small,
                   float*       __restrict__ out)
{
    __shared__ float sx[D_DIM];            // 16 KB: this sample's x row (f32)
    __shared__ float wsum[8][R_LARGE];     // 2 KB: per-warp partial outputs

    const int b    = blockIdx.x;           // 0..511
    const int tid  = threadIdx.x;          // 0..255
    const int warp = tid >> 5;             // 0..7
    const int lane = tid & 31;

    // ---- stage x[b] into shared memory (1024 x float4 loads) ----
    const float4* xv  = (const float4*)(x + (size_t)b * D_DIM);
    float4*       sxv = (float4*)sx;
    #pragma unroll
    for (int i = 0; i < 4; ++i) sxv[tid + 256 * i] = xv[tid + 256 * i];
    __syncthreads();

    if (b < B_LARGE) {
        // ================= large path: R = 64 (row = 256 B) =================
        const int wid = wids_large[b];
        const float* A = A_large + (size_t)wid * D_DIM * R_LARGE;

        const int r0    = (lane & 7) * 8;   // 8 floats per thread in r
        const int dsub  = lane >> 3;        // 0..3: 4 rows per warp per iter
        const int dbase = warp * 512 + dsub;

        float acc[8];
        #pragma unroll
        for (int i = 0; i < 8; ++i) acc[i] = 0.f;

        #pragma unroll 4
        for (int it = 0; it < 128; ++it) {
            const int d = dbase + it * 4;
            const float4* ap = (const float4*)(A + (size_t)d * R_LARGE + r0);
            const float4 a0 = ap[0];
            const float4 a1 = ap[1];
            const float xs = sx[d];
            acc[0] = fmaf(xs, a0.x, acc[0]);
            acc[1] = fmaf(xs, a0.y, acc[1]);
            acc[2] = fmaf(xs, a0.z, acc[2]);
            acc[3] = fmaf(xs, a0.w, acc[3]);
            acc[4] = fmaf(xs, a1.x, acc[4]);
            acc[5] = fmaf(xs, a1.y, acc[5]);
            acc[6] = fmaf(xs, a1.z, acc[6]);
            acc[7] = fmaf(xs, a1.w, acc[7]);
        }

        // reduce over dsub (lane bits 3,4)
        #pragma unroll
        for (int i = 0; i < 8; ++i) {
            acc[i] += __shfl_xor_sync(0xffffffffu, acc[i], 8);
            acc[i] += __shfl_xor_sync(0xffffffffu, acc[i], 16);
        }
        if (lane < 8) {
            #pragma unroll
            for (int i = 0; i < 8; ++i) wsum[warp][r0 + i] = acc[i];
        }
        __syncthreads();

        if (tid < R_LARGE) {
            float s = 0.f;
            #pragma unroll
            for (int w = 0; w < 8; ++w) s += wsum[w][tid];
            out[b * R_LARGE + tid] = s;
        }
    } else {
        // ================= small path: R = 16 (row = 64 B) =================
        const int bs  = b - B_LARGE;
        const int wid = wids_small[bs];
        const float* A = A_small + (size_t)wid * D_DIM * R_SMALL;

        const int r0    = (lane & 1) * 8;   // 2 threads per 64B row
        const int dsub  = lane >> 1;        // 0..15: 16 rows per warp per iter
        const int dbase = warp * 512 + dsub;

        float acc[8];
        #pragma unroll
        for (int i = 0; i < 8; ++i) acc[i] = 0.f;

        #pragma unroll 4
        for (int it = 0; it < 32; ++it) {
            const int d = dbase + it * 16;
            const float4* ap = (const float4*)(A + (size_t)d * R_SMALL + r0);
            const float4 a0 = ap[0];
            const float4 a1 = ap[1];
            const float xs = sx[d];
            acc[0] = fmaf(xs, a0.x, acc[0]);
            acc[1] = fmaf(xs, a0.y, acc[1]);
            acc[2] = fmaf(xs, a0.z, acc[2]);
            acc[3] = fmaf(xs, a0.w, acc[3]);
            acc[4] = fmaf(xs, a1.x, acc[4]);
            acc[5] = fmaf(xs, a1.y, acc[5]);
            acc[6] = fmaf(xs, a1.z, acc[6]);
            acc[7] = fmaf(xs, a1.w, acc[7]);
        }

        // reduce over dsub (lane bits 1..4)
        #pragma unroll
        for (int i = 0; i < 8; ++i) {
            acc[i] += __shfl_xor_sync(0xffffffffu, acc[i], 2);
            acc[i] += __shfl_xor_sync(0xffffffffu, acc[i], 4);
            acc[i] += __shfl_xor_sync(0xffffffffu, acc[i], 8);
            acc[i] += __shfl_xor_sync(0xffffffffu, acc[i], 16);
        }
        if (lane < 2) {
            #pragma unroll
            for (int i = 0; i < 8; ++i) wsum[warp][r0 + i] = acc[i];
        }
        __syncthreads();

        if (tid < R_SMALL) {
            float s = 0.f;
            #pragma unroll
            for (int w = 0; w < 8; ++w) s += wsum[w][tid];
            out[B_LARGE * R_LARGE + bs * R_SMALL + tid] = s;
        }
    }
}

extern "C" void kernel_launch(void* const* d_in, const int* in_sizes, int n_in,
                              void* d_out, int out_size)
{
    const float* x      = nullptr;
    const float* Alarge = nullptr;
    const float* Asmall = nullptr;
    const int*   widl   = nullptr;
    const int*   widsm  = nullptr;

    for (int i = 0; i < n_in; ++i) {
        const int sz = in_sizes[i];
        if (sz == 512 * D_DIM) {
            x = (const float*)d_in[i];
        } else if (sz == 128 * D_DIM * R_LARGE) {
            Alarge = (const float*)d_in[i];
        } else if (sz == 128 * D_DIM * R_SMALL) {
            Asmall = (const float*)d_in[i];
        } else if (sz == 256) {
            if (!widl) widl = (const int*)d_in[i];
            else       widsm = (const int*)d_in[i];
        }
    }

    float* out = (float*)d_out;
    lora_a_kernel<<<B_LARGE + B_SMALL, 256>>>(x, widl, widsm, Alarge, Asmall, out);
}